// round 17
// baseline (speedup 1.0000x reference)
#include <cuda_runtime.h>
#include <cuda_fp16.h>
#include <cstdint>

#define L    4096
#define DM   768
#define NH   12
#define HD   64
#define ATTN_SCALE 0.125f   // folded into Q projection

// ---------------- scratch (no allocations allowed) ----------------
__device__ __align__(16) __half g_Qh[L * DM];    // pre-scaled by 0.125
__device__ __align__(16) __half g_Kh[L * DM];
__device__ __align__(16) __half g_Vh[L * DM];
__device__ __align__(16) __half g_Ah[L * DM];

// =======================================================================
// helpers
// =======================================================================
__device__ __forceinline__ uint32_t f2h2(float lo, float hi) {
    __half2 h = __floats2half2_rn(lo, hi);
    return *(uint32_t*)&h;
}
__device__ __forceinline__ uint32_t ldcvt(const float* p) {   // 2 fp32 -> half2
    const float2 t = *(const float2*)p;
    return f2h2(t.x, t.y);
}
__device__ __forceinline__ void mma_f16(float c[4], const uint32_t a[4], const uint32_t b[2]) {
    asm volatile(
        "mma.sync.aligned.m16n8k16.row.col.f32.f16.f16.f32 "
        "{%0,%1,%2,%3}, {%4,%5,%6,%7}, {%8,%9}, {%0,%1,%2,%3};"
        : "+f"(c[0]), "+f"(c[1]), "+f"(c[2]), "+f"(c[3])
        : "r"(a[0]), "r"(a[1]), "r"(a[2]), "r"(a[3]), "r"(b[0]), "r"(b[1]));
}
__device__ __forceinline__ void ldmx4t(uint32_t r[4], uint32_t addr) {
    asm volatile("ldmatrix.sync.aligned.m8n8.x4.trans.shared.b16 {%0,%1,%2,%3}, [%4];"
        : "=r"(r[0]), "=r"(r[1]), "=r"(r[2]), "=r"(r[3]) : "r"(addr));
}
__device__ __forceinline__ void cp16(uint32_t sdst, const void* gsrc) {
    asm volatile("cp.async.cg.shared.global [%0], [%1], 16;" :: "r"(sdst), "l"(gsrc));
}
#define CP_COMMIT() asm volatile("cp.async.commit_group;" ::: "memory")
#define CP_WAIT0()  asm volatile("cp.async.wait_group 0;" ::: "memory")

// =======================================================================
// qkv GEMM: C = X(fp32) * W(fp32)^T + b, output fp16 (Q scaled by 0.125)
// CTA 256x128, 256 thr, warp tile 64x64 (4x2), 2-stage early-prefetch ring.
// fp32 tiles in smem; fragments converted to fp16 at LDS time.
// =======================================================================
#define BKF 64                                  // K per tile (floats)
#define NT (DM / BKF)                           // 12
#define QSF 68                                  // fp32 row stride (floats)
#define QKV_A_BYTES (256 * QSF * 4)             // 69632
#define QKV_STAGE (QKV_A_BYTES + 128 * QSF * 4) // 104448
#define QKV_SMEM (2 * QKV_STAGE)                // 208896

__device__ __forceinline__ void stage_qkv(uint32_t sbase,
                                          const float* __restrict__ X, int i0,
                                          const float* __restrict__ W, int j0,
                                          int kt, int tid)
{
#pragma unroll
    for (int i = 0; i < 16; ++i) {              // A: 256 rows x 16 chunks
        const int f = tid + i * 256;
        const int r = f >> 4, c = f & 15;
        cp16(sbase + (uint32_t)(r * QSF + c * 4) * 4,
             X + (size_t)(i0 + r) * DM + kt * BKF + c * 4);
    }
#pragma unroll
    for (int i = 0; i < 8; ++i) {               // B: 128 rows x 16 chunks
        const int f = tid + i * 256;
        const int r = f >> 4, c = f & 15;
        cp16(sbase + QKV_A_BYTES + (uint32_t)(r * QSF + c * 4) * 4,
             W + (size_t)(j0 + r) * DM + kt * BKF + c * 4);
    }
}

__global__ void __launch_bounds__(256, 1)
qkv_proj_kernel(const float* __restrict__ xq, const float* __restrict__ xk, const float* __restrict__ xv,
                const float* __restrict__ wq, const float* __restrict__ wk, const float* __restrict__ wv,
                const float* __restrict__ bq, const float* __restrict__ bk, const float* __restrict__ bv)
{
    const int z = blockIdx.z;
    const float* X    = (z == 0) ? xq : (z == 1) ? xk : xv;
    const float* W    = (z == 0) ? wq : (z == 1) ? wk : wv;
    const float* bias = (z == 0) ? bq : (z == 1) ? bk : bv;
    __half* dst       = (z == 0) ? g_Qh : (z == 1) ? g_Kh : g_Vh;
    const float sc    = (z == 0) ? ATTN_SCALE : 1.0f;
    const int i0 = blockIdx.x * 256;
    const int j0 = blockIdx.y * 128;

    extern __shared__ char smc[];
    const uint32_t sb = (uint32_t)__cvta_generic_to_shared(smc);

    const int tid  = threadIdx.x;
    const int wid  = tid >> 5;
    const int lane = tid & 31;
    const int gq   = lane >> 2;
    const int tg   = lane & 3;
    const int wm0  = (wid & 3) * 64;
    const int wn0  = (wid >> 2) * 64;

    float acc[4][8][4] = {};

    stage_qkv(sb, X, i0, W, j0, 0, tid);
    CP_COMMIT();

    int buf = 0;
    for (int kt = 0; kt < NT; ++kt) {
        CP_WAIT0();
        __syncthreads();
        if (kt + 1 < NT) {                      // early prefetch into other buf
            stage_qkv(sb + (uint32_t)(buf ^ 1) * QKV_STAGE, X, i0, W, j0, kt + 1, tid);
            CP_COMMIT();
        }

        const float* Af = (const float*)(smc + buf * QKV_STAGE);
        const float* Bf = Af + 256 * QSF;
#pragma unroll
        for (int kk = 0; kk < BKF; kk += 16) {
            uint32_t af[4][4], bf[8][2];
#pragma unroll
            for (int mt = 0; mt < 4; ++mt) {
                const int r = wm0 + mt * 16 + gq;
                af[mt][0] = ldcvt(&Af[(r    ) * QSF + kk + 2 * tg    ]);
                af[mt][1] = ldcvt(&Af[(r + 8) * QSF + kk + 2 * tg    ]);
                af[mt][2] = ldcvt(&Af[(r    ) * QSF + kk + 2 * tg + 8]);
                af[mt][3] = ldcvt(&Af[(r + 8) * QSF + kk + 2 * tg + 8]);
            }
#pragma unroll
            for (int nt = 0; nt < 8; ++nt) {
                const int n = wn0 + nt * 8 + gq;
                bf[nt][0] = ldcvt(&Bf[n * QSF + kk + 2 * tg    ]);
                bf[nt][1] = ldcvt(&Bf[n * QSF + kk + 2 * tg + 8]);
            }
#pragma unroll
            for (int mt = 0; mt < 4; ++mt)
#pragma unroll
                for (int nt = 0; nt < 8; ++nt)
                    mma_f16(acc[mt][nt], af[mt], bf[nt]);
        }
        buf ^= 1;
    }

#pragma unroll
    for (int nt = 0; nt < 8; ++nt) {
        const int col = j0 + wn0 + nt * 8 + 2 * tg;
        const float2 bb = *(const float2*)&bias[col];
#pragma unroll
        for (int mt = 0; mt < 4; ++mt) {
            const int r = i0 + wm0 + mt * 16 + gq;
            uint32_t h0 = f2h2((acc[mt][nt][0] + bb.x) * sc,
                               (acc[mt][nt][1] + bb.y) * sc);
            uint32_t h1 = f2h2((acc[mt][nt][2] + bb.x) * sc,
                               (acc[mt][nt][3] + bb.y) * sc);
            *(uint32_t*)&dst[(size_t)r * DM + col] = h0;
            *(uint32_t*)&dst[(size_t)(r + 8) * DM + col] = h1;
        }
    }
}

// =======================================================================
// out_proj: C = A(fp16 g_Ah) * Wo(fp32)^T + bo, output fp32.
// CTA 128x192, 128 CTAs -> 1/SM single wave. Warp tile 32x96 (4x2).
// 2-stage early-prefetch ring; A fp16 smem, B fp32 smem (cvt at LDS).
// =======================================================================
#define OSH 72                                  // fp16 A row stride (halfs)
#define OUT_A_BYTES (128 * OSH * 2)             // 18432
#define OUT_STAGE (OUT_A_BYTES + 192 * QSF * 4) // 18432 + 52224 = 70656
#define OUT_SMEM (2 * OUT_STAGE)                // 141312

__device__ __forceinline__ void stage_out(uint32_t sbase,
                                          const __half* __restrict__ A, int i0,
                                          const float* __restrict__ B, int j0,
                                          int kt, int tid)
{
#pragma unroll
    for (int i = 0; i < 4; ++i) {               // A: 128 rows x 8 chunks (fp16)
        const int f = tid + i * 256;
        const int r = f >> 3, c = f & 7;
        cp16(sbase + (uint32_t)(r * OSH + c * 8) * 2,
             A + (size_t)(i0 + r) * DM + kt * BKF + c * 8);
    }
#pragma unroll
    for (int i = 0; i < 12; ++i) {              // B: 192 rows x 16 chunks (fp32)
        const int f = tid + i * 256;
        const int r = f >> 4, c = f & 15;
        cp16(sbase + OUT_A_BYTES + (uint32_t)(r * QSF + c * 4) * 4,
             B + (size_t)(j0 + r) * DM + kt * BKF + c * 4);
    }
}

__global__ void __launch_bounds__(256, 1)
out_proj_kernel(const float* __restrict__ wo, const float* __restrict__ bo,
                float* __restrict__ out)
{
    const int i0 = blockIdx.x * 128;
    const int j0 = blockIdx.y * 192;

    extern __shared__ char smc[];
    const uint32_t sb = (uint32_t)__cvta_generic_to_shared(smc);

    const int tid  = threadIdx.x;
    const int wid  = tid >> 5;
    const int lane = tid & 31;
    const int gq   = lane >> 2;
    const int tg   = lane & 3;
    const int wm0  = (wid & 3) * 32;
    const int wn0  = (wid >> 2) * 96;

    float acc[2][12][4] = {};

    stage_out(sb, g_Ah, i0, wo, j0, 0, tid);
    CP_COMMIT();

    int buf = 0;
    for (int kt = 0; kt < NT; ++kt) {
        CP_WAIT0();
        __syncthreads();
        if (kt + 1 < NT) {
            stage_out(sb + (uint32_t)(buf ^ 1) * OUT_STAGE, g_Ah, i0, wo, j0, kt + 1, tid);
            CP_COMMIT();
        }

        const __half* Ah = (const __half*)(smc + buf * OUT_STAGE);
        const float*  Bf = (const float*)(smc + buf * OUT_STAGE + OUT_A_BYTES);
#pragma unroll
        for (int kk = 0; kk < BKF; kk += 16) {
            uint32_t af[2][4], bf[12][2];
#pragma unroll
            for (int mt = 0; mt < 2; ++mt) {
                const int r = wm0 + mt * 16 + gq;
                af[mt][0] = *(const uint32_t*)&Ah[(r    ) * OSH + kk + 2 * tg    ];
                af[mt][1] = *(const uint32_t*)&Ah[(r + 8) * OSH + kk + 2 * tg    ];
                af[mt][2] = *(const uint32_t*)&Ah[(r    ) * OSH + kk + 2 * tg + 8];
                af[mt][3] = *(const uint32_t*)&Ah[(r + 8) * OSH + kk + 2 * tg + 8];
            }
#pragma unroll
            for (int nt = 0; nt < 12; ++nt) {
                const int n = wn0 + nt * 8 + gq;
                bf[nt][0] = ldcvt(&Bf[n * QSF + kk + 2 * tg    ]);
                bf[nt][1] = ldcvt(&Bf[n * QSF + kk + 2 * tg + 8]);
            }
#pragma unroll
            for (int mt = 0; mt < 2; ++mt)
#pragma unroll
                for (int nt = 0; nt < 12; ++nt)
                    mma_f16(acc[mt][nt], af[mt], bf[nt]);
        }
        buf ^= 1;
    }

#pragma unroll
    for (int nt = 0; nt < 12; ++nt) {
        const int col = j0 + wn0 + nt * 8 + 2 * tg;
        const float2 bb = *(const float2*)&bo[col];
#pragma unroll
        for (int mt = 0; mt < 2; ++mt) {
            const int r = i0 + wm0 + mt * 16 + gq;
            float2 s0 = {acc[mt][nt][0] + bb.x, acc[mt][nt][1] + bb.y};
            float2 s1 = {acc[mt][nt][2] + bb.x, acc[mt][nt][3] + bb.y};
            *(float2*)&out[(size_t)r * DM + col] = s0;
            *(float2*)&out[(size_t)(r + 8) * DM + col] = s1;
        }
    }
}

// =======================================================================
// flash-style sliding-window attention (R12, unchanged)
// =======================================================================
#define AQKH 72
#define AOFF_QS 0
#define AOFF_KS 18432
#define AOFF_VS 55296
#define ATT_SMEM_BYTES (AOFF_VS + 256 * AQKH * 2)   // 92160

__global__ void __launch_bounds__(256, 2)
attn_kernel()
{
    extern __shared__ char smc[];
    __half* Qs = (__half*)(smc + AOFF_QS);
    __half* Ks = (__half*)(smc + AOFF_KS);

    const int tid  = threadIdx.x;
    const int q0   = blockIdx.x * 128;
    const int h    = blockIdx.y;
    const int c0   = h * HD;
    const int wid  = tid >> 5;
    const int lane = tid & 31;
    const int gq   = lane >> 2;
    const int tg   = lane & 3;

    const uint32_t sbase = (uint32_t)__cvta_generic_to_shared(smc);

    {
        const uint32_t sQ = sbase + AOFF_QS;
        const uint32_t sK = sbase + AOFF_KS;
        const uint32_t sV = sbase + AOFF_VS;
#pragma unroll
        for (int i = 0; i < 4; ++i) {
            const int f = tid + i * 256;
            const int q = f >> 3, c = f & 7;
            cp16(sQ + (uint32_t)(q * AQKH + c * 8) * 2,
                 g_Qh + (size_t)(q0 + q) * DM + c0 + c * 8);
        }
#pragma unroll
        for (int i = 0; i < 8; ++i) {
            const int f = tid + i * 256;
            const int j = f >> 3, c = f & 7;
            const int jg = min(max(q0 - 64 + j, 0), L - 1);
            cp16(sK + (uint32_t)(j * AQKH + c * 8) * 2,
                 g_Kh + (size_t)jg * DM + c0 + c * 8);
            cp16(sV + (uint32_t)(j * AQKH + c * 8) * 2,
                 g_Vh + (size_t)jg * DM + c0 + c * 8);
        }
        CP_COMMIT();
    }
    CP_WAIT0();
    __syncthreads();

    const int wm  = wid * 16;
    const int iq0 = q0 + wm + gq;
    const int iq1 = iq0 + 8;
    const int lo0 = max(iq0 - 64, 0), hi0 = min(iq0 + 64, L - 1);
    const int lo1 = max(iq1 - 64, 0), hi1 = min(iq1 + 64, L - 1);

    float oacc[8][4] = {};
    float m0 = -1e30f, m1 = -1e30f;
    float l0 = 0.f,    l1 = 0.f;

    const int jbase0 = (wid >> 2) * 64;
    const int vrow = lane & 15;
    const int vcol = (lane >> 4) * 8;

    for (int cb = 0; cb < 3; ++cb) {
        const int jb = jbase0 + cb * 64;

        float sc[8][4] = {};
#pragma unroll
        for (int kk = 0; kk < 64; kk += 16) {
            uint32_t a[4];
            a[0] = *(const uint32_t*)&Qs[(wm + gq    ) * AQKH + kk + 2 * tg    ];
            a[1] = *(const uint32_t*)&Qs[(wm + gq + 8) * AQKH + kk + 2 * tg    ];
            a[2] = *(const uint32_t*)&Qs[(wm + gq    ) * AQKH + kk + 2 * tg + 8];
            a[3] = *(const uint32_t*)&Qs[(wm + gq + 8) * AQKH + kk + 2 * tg + 8];
#pragma unroll
            for (int nt = 0; nt < 8; ++nt) {
                const int n = jb + nt * 8 + gq;
                uint32_t b[2];
                b[0] = *(const uint32_t*)&Ks[n * AQKH + kk + 2 * tg    ];
                b[1] = *(const uint32_t*)&Ks[n * AQKH + kk + 2 * tg + 8];
                mma_f16(sc[nt], a, b);
            }
        }

        float mn0 = m0, mn1 = m1;
#pragma unroll
        for (int nt = 0; nt < 8; ++nt) {
            const int jg0 = q0 - 64 + jb + nt * 8 + 2 * tg;
#pragma unroll
            for (int e = 0; e < 4; ++e) {
                const int jg = jg0 + (e & 1);
                float s = sc[nt][e];
                if (e < 2) {
                    s = (jg >= lo0 && jg <= hi0) ? s : -1e30f;
                    mn0 = fmaxf(mn0, s);
                } else {
                    s = (jg >= lo1 && jg <= hi1) ? s : -1e30f;
                    mn1 = fmaxf(mn1, s);
                }
                sc[nt][e] = s;
            }
        }
        mn0 = fmaxf(mn0, __shfl_xor_sync(0xffffffffu, mn0, 1));
        mn0 = fmaxf(mn0, __shfl_xor_sync(0xffffffffu, mn0, 2));
        mn1 = fmaxf(mn1, __shfl_xor_sync(0xffffffffu, mn1, 1));
        mn1 = fmaxf(mn1, __shfl_xor_sync(0xffffffffu, mn1, 2));
        const float al0 = __expf(m0 - mn0);
        const float al1 = __expf(m1 - mn1);
        m0 = mn0; m1 = mn1;

        uint32_t ph[8][2];
        float cs0 = 0.f, cs1 = 0.f;
#pragma unroll
        for (int nt = 0; nt < 8; ++nt) {
            const float p0 = __expf(sc[nt][0] - m0);
            const float p1 = __expf(sc[nt][1] - m0);
            const float p2 = __expf(sc[nt][2] - m1);
            const float p3 = __expf(sc[nt][3] - m1);
            ph[nt][0] = f2h2(p0, p1);
            ph[nt][1] = f2h2(p2, p3);
            cs0 += p0 + p1;
            cs1 += p2 + p3;
        }
        cs0 += __shfl_xor_sync(0xffffffffu, cs0, 1);
        cs0 += __shfl_xor_sync(0xffffffffu, cs0, 2);
        cs1 += __shfl_xor_sync(0xffffffffu, cs1, 1);
        cs1 += __shfl_xor_sync(0xffffffffu, cs1, 2);
        l0 = l0 * al0 + cs0;
        l1 = l1 * al1 + cs1;

#pragma unroll
        for (int dnt = 0; dnt < 8; ++dnt) {
            oacc[dnt][0] *= al0; oacc[dnt][1] *= al0;
            oacc[dnt][2] *= al1; oacc[dnt][3] *= al1;
        }

#pragma unroll
        for (int t = 0; t < 4; ++t) {
            uint32_t a[4] = { ph[2 * t][0], ph[2 * t][1],
                              ph[2 * t + 1][0], ph[2 * t + 1][1] };
#pragma unroll
            for (int dt = 0; dt < 4; ++dt) {
                uint32_t bt[4];
                ldmx4t(bt, sbase + AOFF_VS +
                       (uint32_t)((jb + t * 16 + vrow) * AQKH + dt * 16 + vcol) * 2);
                mma_f16(oacc[2 * dt    ], a, &bt[0]);
                mma_f16(oacc[2 * dt + 1], a, &bt[2]);
            }
        }
    }

    const float inv0 = 1.f / l0;
    const float inv1 = 1.f / l1;
#pragma unroll
    for (int dnt = 0; dnt < 8; ++dnt) {
        const int d = dnt * 8 + 2 * tg;
        const uint32_t h0 = f2h2(oacc[dnt][0] * inv0, oacc[dnt][1] * inv0);
        const uint32_t h1 = f2h2(oacc[dnt][2] * inv1, oacc[dnt][3] * inv1);
        *(uint32_t*)&g_Ah[(size_t)iq0 * DM + c0 + d] = h0;
        *(uint32_t*)&g_Ah[(size_t)iq1 * DM + c0 + d] = h1;
    }
}

// ---------------- launch ----------------
extern "C" void kernel_launch(void* const* d_in, const int* in_sizes, int n_in,
                              void* d_out, int out_size)
{
    const float* q  = (const float*)d_in[0];
    const float* k  = (const float*)d_in[1];
    const float* v  = (const float*)d_in[2];
    const float* Wq = (const float*)d_in[3];
    const float* bq = (const float*)d_in[4];
    const float* Wk = (const float*)d_in[5];
    const float* bk = (const float*)d_in[6];
    const float* Wv = (const float*)d_in[7];
    const float* bv = (const float*)d_in[8];
    const float* Wo = (const float*)d_in[9];
    const float* bo = (const float*)d_in[10];
    float* out = (float*)d_out;

    cudaFuncSetAttribute(qkv_proj_kernel,
                         cudaFuncAttributeMaxDynamicSharedMemorySize, QKV_SMEM);
    cudaFuncSetAttribute(out_proj_kernel,
                         cudaFuncAttributeMaxDynamicSharedMemorySize, OUT_SMEM);
    cudaFuncSetAttribute(attn_kernel,
                         cudaFuncAttributeMaxDynamicSharedMemorySize, ATT_SMEM_BYTES);

    qkv_proj_kernel<<<dim3(L / 256, DM / 128, 3), 256, QKV_SMEM>>>(
        q, k, v, Wq, Wk, Wv, bq, bk, bv);
    attn_kernel<<<dim3(L / 128, NH), 256, ATT_SMEM_BYTES>>>();
    out_proj_kernel<<<dim3(L / 128, DM / 192), 256, OUT_SMEM>>>(Wo, bo, out);
}